// round 13
// baseline (speedup 1.0000x reference)
#include <cuda_runtime.h>
#include <cuda_fp16.h>
#include <math.h>

#define N_NODES 50000
#define N_EDGES 800000
#define IN_DIM  256
#define OUT_DIM 64
#define ALPHA   0.2f
#define GAT_EPS 9e-15f

#define SB 256
#define SCAN_NB ((N_NODES + SB - 1) / SB)   // 196

// gemm grid split
#define NGB ((N_NODES + 127) / 128)          // 391 gemm blocks
#define DEGB 256                             // degree-count blocks

// ---------------- scratch ----------------------------------------------------
__device__ __half2      g_hh[N_NODES * 32];           // h in fp16x2: 6.4 MB
__device__ float        g_s[N_NODES];
__device__ float        g_t[N_NODES];
__device__ int          g_deg[N_NODES];               // zero-init; self-resetting
__device__ int          g_off[N_NODES + 1];
__device__ int2         g_ns[N_NODES];                // packed (off, s_bits)
__device__ int          g_rank[N_EDGES];              // edge's rank within its src
__device__ int          g_bsum[SCAN_NB];
__device__ int2         g_csr[N_EDGES];               // (dst, exp_bits) packed
__device__ int          g_cnt;                        // scan ticket (self-resetting)

// packed f32x2 helpers (FFMA2 path — sm_103a)
__device__ __forceinline__ void ffma2(unsigned long long& d,
                                      unsigned long long a,
                                      unsigned long long b) {
    asm("fma.rn.f32x2 %0, %1, %2, %0;" : "+l"(d) : "l"(a), "l"(b));
}
__device__ __forceinline__ unsigned long long dup_f32(float f) {
    unsigned long long r;
    asm("mov.b64 %0, {%1, %1};" : "=l"(r) : "f"(f));
    return r;
}
__device__ __forceinline__ void unpack2(unsigned long long p, float& lo, float& hi) {
    asm("mov.b64 {%0, %1}, %2;" : "=f"(lo), "=f"(hi) : "l"(p));
}

// block-wide exclusive scan over 256 threads
__device__ __forceinline__ int block_excl_scan_256(int v) {
    __shared__ int wt[8];
    const int tid  = threadIdx.x;
    const int lane = tid & 31;
    const int wid  = tid >> 5;
    int inc = v;
#pragma unroll
    for (int o = 1; o < 32; o <<= 1) {
        int y = __shfl_up_sync(0xFFFFFFFFu, inc, o);
        if (lane >= o) inc += y;
    }
    if (lane == 31) wt[wid] = inc;
    __syncthreads();
    if (tid == 0) {
        int r = 0;
#pragma unroll
        for (int w = 0; w < 8; w++) { int t = wt[w]; wt[w] = r; r += t; }
    }
    __syncthreads();
    return inc - v + wt[wid];
}

// ---------------- K1: hybrid — gemm(+s,t) blocks | degree+rank blocks --------
#define GBM 128
#define GBK 32
__global__ void __launch_bounds__(128) gemm_deg_kernel(const float* __restrict__ x,
                                                       const float* __restrict__ W,
                                                       const float* __restrict__ attn,
                                                       const int* __restrict__ edge) {
    __shared__ float xs[GBK][GBM + 4];
    __shared__ float ws[GBK][64];

    if (blockIdx.x >= NGB) {
        // ---- degree-count + rank-capture role ----
        int b = blockIdx.x - NGB;
        for (int e = b * 128 + threadIdx.x; e < N_EDGES; e += DEGB * 128)
            g_rank[e] = atomicAdd(&g_deg[edge[e]], 1);
        return;
    }

    // ---- gemm role ----
    const int tid = threadIdx.x;
    const int tx = tid >> 3;            // 0..15 : m-tile
    const int ty = tid & 7;             // 0..7  : n-tile
    const int block_row = blockIdx.x * GBM;

    unsigned long long acc2[8][4];
#pragma unroll
    for (int i = 0; i < 8; i++)
#pragma unroll
        for (int j = 0; j < 4; j++) acc2[i][j] = 0ull;

    for (int kb = 0; kb < IN_DIM; kb += GBK) {
#pragma unroll
        for (int r = 0; r < 8; r++) {
            int idx = r * 128 + tid;
            int m   = idx >> 3;
            int k4  = (idx & 7) * 4;
            int grow = block_row + m;
            float4 v = make_float4(0.f, 0.f, 0.f, 0.f);
            if (grow < N_NODES)
                v = *reinterpret_cast<const float4*>(&x[(size_t)grow * IN_DIM + kb + k4]);
            xs[k4 + 0][m] = v.x;
            xs[k4 + 1][m] = v.y;
            xs[k4 + 2][m] = v.z;
            xs[k4 + 3][m] = v.w;
        }
#pragma unroll
        for (int r = 0; r < 4; r++) {
            int idx = r * 128 + tid;
            int k   = idx >> 4;
            int n4  = (idx & 15) * 4;
            *reinterpret_cast<float4*>(&ws[k][n4]) =
                *reinterpret_cast<const float4*>(&W[(size_t)(kb + k) * OUT_DIM + n4]);
        }
        __syncthreads();

#pragma unroll
        for (int k = 0; k < GBK; k++) {
            float a[8];
            *reinterpret_cast<float4*>(&a[0]) = *reinterpret_cast<float4*>(&xs[k][tx * 8]);
            *reinterpret_cast<float4*>(&a[4]) = *reinterpret_cast<float4*>(&xs[k][tx * 8 + 4]);
            unsigned long long b2[4];
            float4 bv0 = *reinterpret_cast<float4*>(&ws[k][ty * 8]);
            float4 bv1 = *reinterpret_cast<float4*>(&ws[k][ty * 8 + 4]);
            asm("mov.b64 %0, {%1, %2};" : "=l"(b2[0]) : "f"(bv0.x), "f"(bv0.y));
            asm("mov.b64 %0, {%1, %2};" : "=l"(b2[1]) : "f"(bv0.z), "f"(bv0.w));
            asm("mov.b64 %0, {%1, %2};" : "=l"(b2[2]) : "f"(bv1.x), "f"(bv1.y));
            asm("mov.b64 %0, {%1, %2};" : "=l"(b2[3]) : "f"(bv1.z), "f"(bv1.w));
            unsigned long long ad[8];
#pragma unroll
            for (int i = 0; i < 8; i++) ad[i] = dup_f32(a[i]);
#pragma unroll
            for (int i = 0; i < 8; i++)
#pragma unroll
                for (int j = 0; j < 4; j++) ffma2(acc2[i][j], ad[i], b2[j]);
        }
        __syncthreads();
    }

    float acc[8][8];
#pragma unroll
    for (int i = 0; i < 8; i++)
#pragma unroll
        for (int j = 0; j < 4; j++) unpack2(acc2[i][j], acc[i][2 * j], acc[i][2 * j + 1]);

    // store h as fp16x2 only (aggr is the sole consumer of h)
#pragma unroll
    for (int i = 0; i < 8; i++) {
        int row = block_row + tx * 8 + i;
        if (row < N_NODES) {
            __half2 p[4];
#pragma unroll
            for (int u = 0; u < 4; u++)
                p[u] = __floats2half2_rn(acc[i][2 * u], acc[i][2 * u + 1]);
            // 4 half2 = 16 bytes -> one uint4 (STG.128) store
            *reinterpret_cast<uint4*>(&g_hh[(size_t)row * 32 + ty * 4]) =
                *reinterpret_cast<uint4*>(p);
        }
    }

    float as[8], ad_[8];
#pragma unroll
    for (int j = 0; j < 8; j++) {
        as[j]  = attn[ty * 8 + j];
        ad_[j] = attn[64 + ty * 8 + j];
    }
#pragma unroll
    for (int i = 0; i < 8; i++) {
        float sp = 0.f, tp = 0.f;
#pragma unroll
        for (int j = 0; j < 8; j++) {
            sp = fmaf(acc[i][j], as[j], sp);
            tp = fmaf(acc[i][j], ad_[j], tp);
        }
#pragma unroll
        for (int o = 4; o; o >>= 1) {
            sp += __shfl_xor_sync(0xFFFFFFFFu, sp, o);
            tp += __shfl_xor_sync(0xFFFFFFFFu, tp, o);
        }
        if (ty == 0) {
            int row = block_row + tx * 8 + i;
            if (row < N_NODES) { g_s[row] = sp; g_t[row] = tp; }
        }
    }
}

// ---------------- K2: scanA + fused scanB (last-block) -----------------------
__global__ void __launch_bounds__(SB) scanAB_kernel() {
    __shared__ int s_last;
    int i = blockIdx.x * SB + threadIdx.x;
    int v = 0;
    if (i < N_NODES) {
        v = g_deg[i];
        g_deg[i] = 0;                       // self-reset for next graph replay
    }
    int ex = block_excl_scan_256(v);
    if (i < N_NODES) g_off[i] = ex;         // block-local prefix (patched by scanC)
    if (threadIdx.x == SB - 1) g_bsum[blockIdx.x] = ex + v;
    __syncthreads();
    if (threadIdx.x == 0) {
        __threadfence();
        s_last = (atomicAdd(&g_cnt, 1) == SCAN_NB - 1);
    }
    __syncthreads();
    if (s_last) {
        int t = threadIdx.x;
        int bv = (t < SCAN_NB) ? g_bsum[t] : 0;
        int bex = block_excl_scan_256(bv);
        if (t < SCAN_NB) g_bsum[t] = bex;
        if (t == 0) {
            g_off[N_NODES] = N_EDGES;
            g_cnt = 0;
        }
    }
}

// ---------------- K3: scanC — patch offsets + pack (off, s) ------------------
__global__ void __launch_bounds__(SB) scanC_kernel() {
    int i = blockIdx.x * SB + threadIdx.x;
    if (i < N_NODES) {
        int o = g_off[i] + g_bsum[blockIdx.x];
        g_off[i] = o;
        g_ns[i] = make_int2(o, __float_as_int(g_s[i]));
    }
}

// ---------------- K4: CSR fill, atomic-free, stores exp directly -------------
__global__ void __launch_bounds__(256) fill_kernel(const int* __restrict__ edge) {
    int e = blockIdx.x * 256 + threadIdx.x;
    if (e >= N_EDGES) return;
    int src  = edge[e];
    int dst  = edge[N_EDGES + e];
    int rank = g_rank[e];
    int2 ns  = g_ns[src];                      // one 8B random load: (off, s)
    float v  = __int_as_float(ns.y) + g_t[dst];
    float a  = (v >= 0.0f) ? v : ALPHA * v;
    // no global-max subtraction: exp(a) stays in fp32 range; deviation vs
    // reference bounded by ~EPS/rowsum ~ 1e-6 << 1e-3 tolerance
    g_csr[ns.x + rank] = make_int2(dst, __float_as_int(__expf(a)));
}

// ---------------- K5: warp-per-node aggregate, fp16 gathers, unroll 4 --------
__global__ void aggr_kernel(float* __restrict__ out) {
    int gid  = blockIdx.x * blockDim.x + threadIdx.x;
    int node = gid >> 5;
    int lane = gid & 31;
    if (node >= N_NODES) return;

    int beg = g_off[node];
    int end = g_off[node + 1];

    const __half2* __restrict__ hh = g_hh;
    float ax = 0.f, ay = 0.f;
    float rs = 0.f;

    int j = beg;
    for (; j + 4 <= end; j += 4) {
        int2 q0 = g_csr[j + 0], q1 = g_csr[j + 1];
        int2 q2 = g_csr[j + 2], q3 = g_csr[j + 3];
        float e0 = __int_as_float(q0.y);
        float e1 = __int_as_float(q1.y);
        float e2 = __int_as_float(q2.y);
        float e3 = __int_as_float(q3.y);
        rs += (e0 + e1) + (e2 + e3);
        float2 v0 = __half22float2(hh[(size_t)q0.x * 32 + lane]);
        float2 v1 = __half22float2(hh[(size_t)q1.x * 32 + lane]);
        float2 v2 = __half22float2(hh[(size_t)q2.x * 32 + lane]);
        float2 v3 = __half22float2(hh[(size_t)q3.x * 32 + lane]);
        ax = fmaf(e0, v0.x, ax); ay = fmaf(e0, v0.y, ay);
        ax = fmaf(e1, v1.x, ax); ay = fmaf(e1, v1.y, ay);
        ax = fmaf(e2, v2.x, ax); ay = fmaf(e2, v2.y, ay);
        ax = fmaf(e3, v3.x, ax); ay = fmaf(e3, v3.y, ay);
    }
    for (; j < end; j++) {
        int2 q = g_csr[j];
        float e = __int_as_float(q.y);
        rs += e;
        float2 v = __half22float2(hh[(size_t)q.x * 32 + lane]);
        ax = fmaf(e, v.x, ax); ay = fmaf(e, v.y, ay);
    }
    float inv = 1.0f / (rs + GAT_EPS);
    reinterpret_cast<float2*>(out)[(size_t)node * 32 + lane] =
        make_float2(ax * inv, ay * inv);
}

// ---------------- launch ------------------------------------------------------
extern "C" void kernel_launch(void* const* d_in, const int* in_sizes, int n_in,
                              void* d_out, int out_size) {
    const float* x    = (const float*)d_in[0];
    const int*   edge = (const int*)  d_in[1];
    const float* W    = (const float*)d_in[2];
    const float* attn = (const float*)d_in[3];
    float*       out  = (float*)d_out;

    gemm_deg_kernel<<<NGB + DEGB, 128>>>(x, W, attn, edge);
    scanAB_kernel<<<SCAN_NB, SB>>>();
    scanC_kernel<<<SCAN_NB, SB>>>();
    fill_kernel<<<(N_EDGES + 255) / 256, 256>>>(edge);
    aggr_kernel<<<(N_NODES * 32 + 255) / 256, 256>>>(out);
}

// round 14
// speedup vs baseline: 1.0989x; 1.0989x over previous
#include <cuda_runtime.h>
#include <math.h>

#define N_NODES 50000
#define N_EDGES 800000
#define IN_DIM  256
#define OUT_DIM 64
#define ALPHA   0.2f
#define GAT_EPS 9e-15f

#define SB 256
#define SCAN_NB ((N_NODES + SB - 1) / SB)   // 196

// gemm grid split
#define NGB ((N_NODES + 127) / 128)          // 391 gemm blocks
#define DEGB 256                             // degree-count blocks

// ---------------- scratch ----------------------------------------------------
__device__ float              g_h[N_NODES * OUT_DIM];   // 12.8 MB fp32
__device__ float              g_s[N_NODES];
__device__ float              g_t[N_NODES];
__device__ int                g_deg[N_NODES];           // zero-init; self-resetting
__device__ int                g_off[N_NODES + 1];
__device__ int2               g_ns[N_NODES];            // packed (off, s_bits)
__device__ int                g_rank[N_EDGES];
__device__ unsigned long long g_state[SCAN_NB];         // lookback: flag<<32 | sum
__device__ int2               g_csr[N_EDGES];           // (dst, exp_bits)
__device__ int                g_cnt;                    // ticket (self-resetting)

// packed f32x2 helpers (FFMA2 path — sm_103a)
__device__ __forceinline__ void ffma2(unsigned long long& d,
                                      unsigned long long a,
                                      unsigned long long b) {
    asm("fma.rn.f32x2 %0, %1, %2, %0;" : "+l"(d) : "l"(a), "l"(b));
}
__device__ __forceinline__ unsigned long long dup_f32(float f) {
    unsigned long long r;
    asm("mov.b64 %0, {%1, %1};" : "=l"(r) : "f"(f));
    return r;
}
__device__ __forceinline__ void unpack2(unsigned long long p, float& lo, float& hi) {
    asm("mov.b64 {%0, %1}, %2;" : "=f"(lo), "=f"(hi) : "l"(p));
}

// block-wide exclusive scan over 256 threads
__device__ __forceinline__ int block_excl_scan_256(int v) {
    __shared__ int wt[8];
    const int tid  = threadIdx.x;
    const int lane = tid & 31;
    const int wid  = tid >> 5;
    int inc = v;
#pragma unroll
    for (int o = 1; o < 32; o <<= 1) {
        int y = __shfl_up_sync(0xFFFFFFFFu, inc, o);
        if (lane >= o) inc += y;
    }
    if (lane == 31) wt[wid] = inc;
    __syncthreads();
    if (tid == 0) {
        int r = 0;
#pragma unroll
        for (int w = 0; w < 8; w++) { int t = wt[w]; wt[w] = r; r += t; }
    }
    __syncthreads();
    return inc - v + wt[wid];
}

// ---------------- K1: hybrid — gemm(+s,t) blocks | degree+rank blocks --------
#define GBM 128
#define GBK 32
__global__ void __launch_bounds__(128) gemm_deg_kernel(const float* __restrict__ x,
                                                       const float* __restrict__ W,
                                                       const float* __restrict__ attn,
                                                       const int* __restrict__ edge) {
    __shared__ float xs[GBK][GBM + 4];
    __shared__ float ws[GBK][64];

    if (blockIdx.x >= NGB) {
        // ---- degree-count + rank-capture role ----
        int b = blockIdx.x - NGB;
        for (int e = b * 128 + threadIdx.x; e < N_EDGES; e += DEGB * 128)
            g_rank[e] = atomicAdd(&g_deg[edge[e]], 1);
        return;
    }

    // ---- gemm role ----
    const int tid = threadIdx.x;
    const int tx = tid >> 3;            // 0..15 : m-tile
    const int ty = tid & 7;             // 0..7  : n-tile
    const int block_row = blockIdx.x * GBM;

    unsigned long long acc2[8][4];
#pragma unroll
    for (int i = 0; i < 8; i++)
#pragma unroll
        for (int j = 0; j < 4; j++) acc2[i][j] = 0ull;

    for (int kb = 0; kb < IN_DIM; kb += GBK) {
#pragma unroll
        for (int r = 0; r < 8; r++) {
            int idx = r * 128 + tid;
            int m   = idx >> 3;
            int k4  = (idx & 7) * 4;
            int grow = block_row + m;
            float4 v = make_float4(0.f, 0.f, 0.f, 0.f);
            if (grow < N_NODES)
                v = *reinterpret_cast<const float4*>(&x[(size_t)grow * IN_DIM + kb + k4]);
            xs[k4 + 0][m] = v.x;
            xs[k4 + 1][m] = v.y;
            xs[k4 + 2][m] = v.z;
            xs[k4 + 3][m] = v.w;
        }
#pragma unroll
        for (int r = 0; r < 4; r++) {
            int idx = r * 128 + tid;
            int k   = idx >> 4;
            int n4  = (idx & 15) * 4;
            *reinterpret_cast<float4*>(&ws[k][n4]) =
                *reinterpret_cast<const float4*>(&W[(size_t)(kb + k) * OUT_DIM + n4]);
        }
        __syncthreads();

#pragma unroll
        for (int k = 0; k < GBK; k++) {
            float a[8];
            *reinterpret_cast<float4*>(&a[0]) = *reinterpret_cast<float4*>(&xs[k][tx * 8]);
            *reinterpret_cast<float4*>(&a[4]) = *reinterpret_cast<float4*>(&xs[k][tx * 8 + 4]);
            unsigned long long b2[4];
            float4 bv0 = *reinterpret_cast<float4*>(&ws[k][ty * 8]);
            float4 bv1 = *reinterpret_cast<float4*>(&ws[k][ty * 8 + 4]);
            asm("mov.b64 %0, {%1, %2};" : "=l"(b2[0]) : "f"(bv0.x), "f"(bv0.y));
            asm("mov.b64 %0, {%1, %2};" : "=l"(b2[1]) : "f"(bv0.z), "f"(bv0.w));
            asm("mov.b64 %0, {%1, %2};" : "=l"(b2[2]) : "f"(bv1.x), "f"(bv1.y));
            asm("mov.b64 %0, {%1, %2};" : "=l"(b2[3]) : "f"(bv1.z), "f"(bv1.w));
            unsigned long long ad[8];
#pragma unroll
            for (int i = 0; i < 8; i++) ad[i] = dup_f32(a[i]);
#pragma unroll
            for (int i = 0; i < 8; i++)
#pragma unroll
                for (int j = 0; j < 4; j++) ffma2(acc2[i][j], ad[i], b2[j]);
        }
        __syncthreads();
    }

    float acc[8][8];
#pragma unroll
    for (int i = 0; i < 8; i++)
#pragma unroll
        for (int j = 0; j < 4; j++) unpack2(acc2[i][j], acc[i][2 * j], acc[i][2 * j + 1]);

#pragma unroll
    for (int i = 0; i < 8; i++) {
        int row = block_row + tx * 8 + i;
        if (row < N_NODES) {
            float4 v0 = make_float4(acc[i][0], acc[i][1], acc[i][2], acc[i][3]);
            float4 v1 = make_float4(acc[i][4], acc[i][5], acc[i][6], acc[i][7]);
            *reinterpret_cast<float4*>(&g_h[(size_t)row * OUT_DIM + ty * 8])     = v0;
            *reinterpret_cast<float4*>(&g_h[(size_t)row * OUT_DIM + ty * 8 + 4]) = v1;
        }
    }

    float as[8], ad_[8];
#pragma unroll
    for (int j = 0; j < 8; j++) {
        as[j]  = attn[ty * 8 + j];
        ad_[j] = attn[64 + ty * 8 + j];
    }
#pragma unroll
    for (int i = 0; i < 8; i++) {
        float sp = 0.f, tp = 0.f;
#pragma unroll
        for (int j = 0; j < 8; j++) {
            sp = fmaf(acc[i][j], as[j], sp);
            tp = fmaf(acc[i][j], ad_[j], tp);
        }
#pragma unroll
        for (int o = 4; o; o >>= 1) {
            sp += __shfl_xor_sync(0xFFFFFFFFu, sp, o);
            tp += __shfl_xor_sync(0xFFFFFFFFu, tp, o);
        }
        if (ty == 0) {
            int row = block_row + tx * 8 + i;
            if (row < N_NODES) { g_s[row] = sp; g_t[row] = tp; }
        }
    }
}

// ---------------- K2: fused scan — decoupled lookback, writes off + ns -------
__global__ void __launch_bounds__(SB) scan_fused_kernel() {
    __shared__ int s_prefix;
    __shared__ int s_total;

    int i = blockIdx.x * SB + threadIdx.x;
    int v = 0;
    if (i < N_NODES) {
        v = g_deg[i];
        g_deg[i] = 0;                        // self-reset for next replay
    }
    int ex = block_excl_scan_256(v);
    if (threadIdx.x == SB - 1) s_total = ex + v;
    __syncthreads();
    int total = s_total;

    if (threadIdx.x == 0) {
        if (blockIdx.x == 0) {
            atomicExch(&g_state[0], (2ull << 32) | (unsigned)total);
            s_prefix = 0;
        } else {
            atomicExch(&g_state[blockIdx.x], (1ull << 32) | (unsigned)total);
            int prefix = 0;
            int b = blockIdx.x - 1;
            while (true) {
                unsigned long long st = atomicAdd(&g_state[b], 0ull);
                unsigned flag = (unsigned)(st >> 32);
                if (flag == 0u) continue;            // not yet published
                prefix += (int)(unsigned)st;
                if (flag == 2u) break;               // inclusive prefix found
                b--;                                 // aggregate only; keep looking
            }
            atomicExch(&g_state[blockIdx.x], (2ull << 32) | (unsigned)(prefix + total));
            s_prefix = prefix;
        }
    }
    __syncthreads();

    int off = ex + s_prefix;
    if (i < N_NODES) {
        g_off[i] = off;
        g_ns[i] = make_int2(off, __float_as_int(g_s[i]));
    }

    // completion ticket: last block cleans state for the next graph replay
    __syncthreads();
    if (threadIdx.x == 0) {
        __threadfence();
        if (atomicAdd(&g_cnt, 1) == SCAN_NB - 1) {
            for (int b = 0; b < SCAN_NB; b++) g_state[b] = 0ull;
            g_off[N_NODES] = N_EDGES;
            g_cnt = 0;
        }
    }
}

// ---------------- K3: CSR fill, atomic-free, stores exp directly -------------
__global__ void __launch_bounds__(256) fill_kernel(const int* __restrict__ edge) {
    int e = blockIdx.x * 256 + threadIdx.x;
    if (e >= N_EDGES) return;
    int src  = edge[e];
    int dst  = edge[N_EDGES + e];
    int rank = g_rank[e];
    int2 ns  = g_ns[src];                      // one 8B random load: (off, s)
    float v  = __int_as_float(ns.y) + g_t[dst];
    float a  = (v >= 0.0f) ? v : ALPHA * v;
    // no global-max subtraction: exp(a) stays in fp32 range; deviation vs
    // reference bounded by ~EPS/rowsum ~ 1e-6 << 1e-3 tolerance
    g_csr[ns.x + rank] = make_int2(dst, __float_as_int(__expf(a)));
}

// ---------------- K4: warp-per-node aggregate, fp32 gathers, unroll 4 --------
__global__ void aggr_kernel(float* __restrict__ out) {
    int gid  = blockIdx.x * blockDim.x + threadIdx.x;
    int node = gid >> 5;
    int lane = gid & 31;
    if (node >= N_NODES) return;

    int beg = g_off[node];
    int end = g_off[node + 1];

    const float2* __restrict__ h2 = reinterpret_cast<const float2*>(g_h);
    float ax = 0.f, ay = 0.f;
    float rs = 0.f;

    int j = beg;
    for (; j + 4 <= end; j += 4) {
        int2 q0 = g_csr[j + 0], q1 = g_csr[j + 1];
        int2 q2 = g_csr[j + 2], q3 = g_csr[j + 3];
        float e0 = __int_as_float(q0.y);
        float e1 = __int_as_float(q1.y);
        float e2 = __int_as_float(q2.y);
        float e3 = __int_as_float(q3.y);
        rs += (e0 + e1) + (e2 + e3);
        float2 v0 = h2[(size_t)q0.x * 32 + lane];
        float2 v1 = h2[(size_t)q1.x * 32 + lane];
        float2 v2 = h2[(size_t)q2.x * 32 + lane];
        float2 v3 = h2[(size_t)q3.x * 32 + lane];
        ax = fmaf(e0, v0.x, ax); ay = fmaf(e0, v0.y, ay);
        ax = fmaf(e1, v1.x, ax); ay = fmaf(e1, v1.y, ay);
        ax = fmaf(e2, v2.x, ax); ay = fmaf(e2, v2.y, ay);
        ax = fmaf(e3, v3.x, ax); ay = fmaf(e3, v3.y, ay);
    }
    for (; j < end; j++) {
        int2 q = g_csr[j];
        float e = __int_as_float(q.y);
        rs += e;
        float2 v = h2[(size_t)q.x * 32 + lane];
        ax = fmaf(e, v.x, ax); ay = fmaf(e, v.y, ay);
    }
    float inv = 1.0f / (rs + GAT_EPS);
    reinterpret_cast<float2*>(out)[(size_t)node * 32 + lane] =
        make_float2(ax * inv, ay * inv);
}

// ---------------- launch ------------------------------------------------------
extern "C" void kernel_launch(void* const* d_in, const int* in_sizes, int n_in,
                              void* d_out, int out_size) {
    const float* x    = (const float*)d_in[0];
    const int*   edge = (const int*)  d_in[1];
    const float* W    = (const float*)d_in[2];
    const float* attn = (const float*)d_in[3];
    float*       out  = (float*)d_out;

    gemm_deg_kernel<<<NGB + DEGB, 128>>>(x, W, attn, edge);
    scan_fused_kernel<<<SCAN_NB, SB>>>();
    fill_kernel<<<(N_EDGES + 255) / 256, 256>>>(edge);
    aggr_kernel<<<(N_NODES * 32 + 255) / 256, 256>>>(out);
}

// round 15
// speedup vs baseline: 1.2038x; 1.0954x over previous
#include <cuda_runtime.h>
#include <math.h>

#define N_NODES 50000
#define N_EDGES 800000
#define IN_DIM  256
#define OUT_DIM 64
#define ALPHA   0.2f
#define GAT_EPS 9e-15f

#define SB 256
#define SCAN_NB ((N_NODES + SB - 1) / SB)   // 196

// gemm grid split
#define NGB ((N_NODES + 127) / 128)          // 391 gemm blocks
#define DEGB 256                             // degree-count blocks

// ---------------- scratch ----------------------------------------------------
__device__ float        g_h[N_NODES * OUT_DIM];       // 12.8 MB fp32
__device__ float        g_s[N_NODES];
__device__ float        g_t[N_NODES];
__device__ int          g_deg[N_NODES];               // zero-init; self-resetting
__device__ int          g_off[N_NODES + 1];
__device__ int2         g_ns[N_NODES];                // packed (off, s_bits)
__device__ int          g_rank[N_EDGES];              // edge's rank within its src
__device__ int          g_bsum[SCAN_NB];
__device__ int2         g_csr[N_EDGES];               // (dst, exp_bits) packed
__device__ int          g_cnt;                        // scan ticket (self-resetting)

// packed f32x2 helpers (FFMA2 path — sm_103a)
__device__ __forceinline__ void ffma2(unsigned long long& d,
                                      unsigned long long a,
                                      unsigned long long b) {
    asm("fma.rn.f32x2 %0, %1, %2, %0;" : "+l"(d) : "l"(a), "l"(b));
}
__device__ __forceinline__ unsigned long long dup_f32(float f) {
    unsigned long long r;
    asm("mov.b64 %0, {%1, %1};" : "=l"(r) : "f"(f));
    return r;
}
__device__ __forceinline__ void unpack2(unsigned long long p, float& lo, float& hi) {
    asm("mov.b64 {%0, %1}, %2;" : "=f"(lo), "=f"(hi) : "l"(p));
}

// block-wide exclusive scan over 256 threads
__device__ __forceinline__ int block_excl_scan_256(int v) {
    __shared__ int wt[8];
    const int tid  = threadIdx.x;
    const int lane = tid & 31;
    const int wid  = tid >> 5;
    int inc = v;
#pragma unroll
    for (int o = 1; o < 32; o <<= 1) {
        int y = __shfl_up_sync(0xFFFFFFFFu, inc, o);
        if (lane >= o) inc += y;
    }
    if (lane == 31) wt[wid] = inc;
    __syncthreads();
    if (tid == 0) {
        int r = 0;
#pragma unroll
        for (int w = 0; w < 8; w++) { int t = wt[w]; wt[w] = r; r += t; }
    }
    __syncthreads();
    return inc - v + wt[wid];
}

// ---------------- K1: hybrid — gemm(+s,t) blocks | degree+rank blocks --------
#define GBM 128
#define GBK 32
__global__ void __launch_bounds__(128) gemm_deg_kernel(const float* __restrict__ x,
                                                       const float* __restrict__ W,
                                                       const float* __restrict__ attn,
                                                       const int* __restrict__ edge) {
    __shared__ float xs[GBK][GBM + 4];
    __shared__ float ws[GBK][64];

    if (blockIdx.x >= NGB) {
        // ---- degree-count + rank-capture role ----
        int b = blockIdx.x - NGB;
        for (int e = b * 128 + threadIdx.x; e < N_EDGES; e += DEGB * 128)
            g_rank[e] = atomicAdd(&g_deg[edge[e]], 1);
        return;
    }

    // ---- gemm role ----
    const int tid = threadIdx.x;
    const int tx = tid >> 3;            // 0..15 : m-tile
    const int ty = tid & 7;             // 0..7  : n-tile
    const int block_row = blockIdx.x * GBM;

    unsigned long long acc2[8][4];
#pragma unroll
    for (int i = 0; i < 8; i++)
#pragma unroll
        for (int j = 0; j < 4; j++) acc2[i][j] = 0ull;

    for (int kb = 0; kb < IN_DIM; kb += GBK) {
#pragma unroll
        for (int r = 0; r < 8; r++) {
            int idx = r * 128 + tid;
            int m   = idx >> 3;
            int k4  = (idx & 7) * 4;
            int grow = block_row + m;
            float4 v = make_float4(0.f, 0.f, 0.f, 0.f);
            if (grow < N_NODES)
                v = *reinterpret_cast<const float4*>(&x[(size_t)grow * IN_DIM + kb + k4]);
            xs[k4 + 0][m] = v.x;
            xs[k4 + 1][m] = v.y;
            xs[k4 + 2][m] = v.z;
            xs[k4 + 3][m] = v.w;
        }
#pragma unroll
        for (int r = 0; r < 4; r++) {
            int idx = r * 128 + tid;
            int k   = idx >> 4;
            int n4  = (idx & 15) * 4;
            *reinterpret_cast<float4*>(&ws[k][n4]) =
                *reinterpret_cast<const float4*>(&W[(size_t)(kb + k) * OUT_DIM + n4]);
        }
        __syncthreads();

#pragma unroll
        for (int k = 0; k < GBK; k++) {
            float a[8];
            *reinterpret_cast<float4*>(&a[0]) = *reinterpret_cast<float4*>(&xs[k][tx * 8]);
            *reinterpret_cast<float4*>(&a[4]) = *reinterpret_cast<float4*>(&xs[k][tx * 8 + 4]);
            unsigned long long b2[4];
            float4 bv0 = *reinterpret_cast<float4*>(&ws[k][ty * 8]);
            float4 bv1 = *reinterpret_cast<float4*>(&ws[k][ty * 8 + 4]);
            asm("mov.b64 %0, {%1, %2};" : "=l"(b2[0]) : "f"(bv0.x), "f"(bv0.y));
            asm("mov.b64 %0, {%1, %2};" : "=l"(b2[1]) : "f"(bv0.z), "f"(bv0.w));
            asm("mov.b64 %0, {%1, %2};" : "=l"(b2[2]) : "f"(bv1.x), "f"(bv1.y));
            asm("mov.b64 %0, {%1, %2};" : "=l"(b2[3]) : "f"(bv1.z), "f"(bv1.w));
            unsigned long long ad[8];
#pragma unroll
            for (int i = 0; i < 8; i++) ad[i] = dup_f32(a[i]);
#pragma unroll
            for (int i = 0; i < 8; i++)
#pragma unroll
                for (int j = 0; j < 4; j++) ffma2(acc2[i][j], ad[i], b2[j]);
        }
        __syncthreads();
    }

    float acc[8][8];
#pragma unroll
    for (int i = 0; i < 8; i++)
#pragma unroll
        for (int j = 0; j < 4; j++) unpack2(acc2[i][j], acc[i][2 * j], acc[i][2 * j + 1]);

#pragma unroll
    for (int i = 0; i < 8; i++) {
        int row = block_row + tx * 8 + i;
        if (row < N_NODES) {
            float4 v0 = make_float4(acc[i][0], acc[i][1], acc[i][2], acc[i][3]);
            float4 v1 = make_float4(acc[i][4], acc[i][5], acc[i][6], acc[i][7]);
            *reinterpret_cast<float4*>(&g_h[(size_t)row * OUT_DIM + ty * 8])     = v0;
            *reinterpret_cast<float4*>(&g_h[(size_t)row * OUT_DIM + ty * 8 + 4]) = v1;
        }
    }

    float as[8], ad_[8];
#pragma unroll
    for (int j = 0; j < 8; j++) {
        as[j]  = attn[ty * 8 + j];
        ad_[j] = attn[64 + ty * 8 + j];
    }
#pragma unroll
    for (int i = 0; i < 8; i++) {
        float sp = 0.f, tp = 0.f;
#pragma unroll
        for (int j = 0; j < 8; j++) {
            sp = fmaf(acc[i][j], as[j], sp);
            tp = fmaf(acc[i][j], ad_[j], tp);
        }
#pragma unroll
        for (int o = 4; o; o >>= 1) {
            sp += __shfl_xor_sync(0xFFFFFFFFu, sp, o);
            tp += __shfl_xor_sync(0xFFFFFFFFu, tp, o);
        }
        if (ty == 0) {
            int row = block_row + tx * 8 + i;
            if (row < N_NODES) { g_s[row] = sp; g_t[row] = tp; }
        }
    }
}

// ---------------- K2: scanA + fused scanB (last-block) -----------------------
__global__ void __launch_bounds__(SB) scanAB_kernel() {
    __shared__ int s_last;
    int i = blockIdx.x * SB + threadIdx.x;
    int v = 0;
    if (i < N_NODES) {
        v = g_deg[i];
        g_deg[i] = 0;                       // self-reset for next graph replay
    }
    int ex = block_excl_scan_256(v);
    if (i < N_NODES) g_off[i] = ex;         // block-local prefix (patched by scanC)
    if (threadIdx.x == SB - 1) g_bsum[blockIdx.x] = ex + v;
    __syncthreads();
    if (threadIdx.x == 0) {
        __threadfence();
        s_last = (atomicAdd(&g_cnt, 1) == SCAN_NB - 1);
    }
    __syncthreads();
    if (s_last) {
        int t = threadIdx.x;
        int bv = (t < SCAN_NB) ? g_bsum[t] : 0;
        int bex = block_excl_scan_256(bv);
        if (t < SCAN_NB) g_bsum[t] = bex;
        if (t == 0) {
            g_off[N_NODES] = N_EDGES;
            g_cnt = 0;
        }
    }
}

// ---------------- K3: scanC — patch offsets + pack (off, s) ------------------
__global__ void __launch_bounds__(SB) scanC_kernel() {
    int i = blockIdx.x * SB + threadIdx.x;
    if (i < N_NODES) {
        int o = g_off[i] + g_bsum[blockIdx.x];
        g_off[i] = o;
        g_ns[i] = make_int2(o, __float_as_int(g_s[i]));
    }
}

// ---------------- K4: CSR fill, atomic-free, stores exp directly -------------
__global__ void __launch_bounds__(256) fill_kernel(const int* __restrict__ edge) {
    int e = blockIdx.x * 256 + threadIdx.x;
    if (e >= N_EDGES) return;
    int src  = edge[e];
    int dst  = edge[N_EDGES + e];
    int rank = g_rank[e];
    int2 ns  = g_ns[src];                      // one 8B random load: (off, s)
    float v  = __int_as_float(ns.y) + g_t[dst];
    float a  = (v >= 0.0f) ? v : ALPHA * v;
    // no global-max subtraction: exp(a) stays in fp32 range; deviation vs
    // reference bounded by ~EPS/rowsum ~ 1e-6 << 1e-3 tolerance
    g_csr[ns.x + rank] = make_int2(dst, __float_as_int(__expf(a)));
}

// ---------------- K5: half-warp-per-node aggregate, float4 lanes, unroll 4 ---
__global__ void aggr_kernel(float* __restrict__ out) {
    int gid  = blockIdx.x * blockDim.x + threadIdx.x;
    int node = gid >> 4;                 // 16 lanes per node
    int lane = gid & 15;                 // lane covers 4 floats
    if (node >= N_NODES) return;

    int beg = g_off[node];
    int end = g_off[node + 1];

    const float4* __restrict__ h4 = reinterpret_cast<const float4*>(g_h);
    float4 acc = make_float4(0.f, 0.f, 0.f, 0.f);
    float rs = 0.f;

    int j = beg;
    for (; j + 4 <= end; j += 4) {
        int2 q0 = g_csr[j + 0], q1 = g_csr[j + 1];
        int2 q2 = g_csr[j + 2], q3 = g_csr[j + 3];
        float e0 = __int_as_float(q0.y);
        float e1 = __int_as_float(q1.y);
        float e2 = __int_as_float(q2.y);
        float e3 = __int_as_float(q3.y);
        rs += (e0 + e1) + (e2 + e3);
        float4 v0 = h4[(size_t)q0.x * 16 + lane];
        float4 v1 = h4[(size_t)q1.x * 16 + lane];
        float4 v2 = h4[(size_t)q2.x * 16 + lane];
        float4 v3 = h4[(size_t)q3.x * 16 + lane];
        acc.x = fmaf(e0, v0.x, acc.x); acc.y = fmaf(e0, v0.y, acc.y);
        acc.z = fmaf(e0, v0.z, acc.z); acc.w = fmaf(e0, v0.w, acc.w);
        acc.x = fmaf(e1, v1.x, acc.x); acc.y = fmaf(e1, v1.y, acc.y);
        acc.z = fmaf(e1, v1.z, acc.z); acc.w = fmaf(e1, v1.w, acc.w);
        acc.x = fmaf(e2, v2.x, acc.x); acc.y = fmaf(e2, v2.y, acc.y);
        acc.z = fmaf(e2, v2.z, acc.z); acc.w = fmaf(e2, v2.w, acc.w);
        acc.x = fmaf(e3, v3.x, acc.x); acc.y = fmaf(e3, v3.y, acc.y);
        acc.z = fmaf(e3, v3.z, acc.z); acc.w = fmaf(e3, v3.w, acc.w);
    }
    for (; j < end; j++) {
        int2 q = g_csr[j];
        float e = __int_as_float(q.y);
        rs += e;
        float4 v = h4[(size_t)q.x * 16 + lane];
        acc.x = fmaf(e, v.x, acc.x); acc.y = fmaf(e, v.y, acc.y);
        acc.z = fmaf(e, v.z, acc.z); acc.w = fmaf(e, v.w, acc.w);
    }
    float inv = 1.0f / (rs + GAT_EPS);
    reinterpret_cast<float4*>(out)[(size_t)node * 16 + lane] =
        make_float4(acc.x * inv, acc.y * inv, acc.z * inv, acc.w * inv);
}

// ---------------- launch ------------------------------------------------------
extern "C" void kernel_launch(void* const* d_in, const int* in_sizes, int n_in,
                              void* d_out, int out_size) {
    const float* x    = (const float*)d_in[0];
    const int*   edge = (const int*)  d_in[1];
    const float* W    = (const float*)d_in[2];
    const float* attn = (const float*)d_in[3];
    float*       out  = (float*)d_out;

    gemm_deg_kernel<<<NGB + DEGB, 128>>>(x, W, attn, edge);
    scanAB_kernel<<<SCAN_NB, SB>>>();
    scanC_kernel<<<SCAN_NB, SB>>>();
    fill_kernel<<<(N_EDGES + 255) / 256, 256>>>(edge);
    aggr_kernel<<<(N_NODES * 16 + 255) / 256, 256>>>(out);
}

// round 16
// speedup vs baseline: 1.2214x; 1.0146x over previous
#include <cuda_runtime.h>
#include <math.h>

#define N_NODES 50000
#define N_EDGES 800000
#define IN_DIM  256
#define OUT_DIM 64
#define ALPHA   0.2f
#define GAT_EPS 9e-15f

#define SB 256
#define SCAN_NB ((N_NODES + SB - 1) / SB)   // 196

// gemm grid split
#define NGB ((N_NODES + 127) / 128)          // 391 gemm blocks
#define DEGB 256                             // degree-count blocks

// ---------------- scratch ----------------------------------------------------
__device__ float        g_h[N_NODES * OUT_DIM];       // 12.8 MB fp32
__device__ float        g_s[N_NODES];
__device__ float        g_t[N_NODES];
__device__ int          g_deg[N_NODES];               // zero-init; self-resetting
__device__ int          g_off[N_NODES + 1];           // LOCAL prefixes (+ bsum at use)
__device__ int2         g_ns[N_NODES];                // packed (local off, s_bits)
__device__ int          g_rank[N_EDGES];              // edge's rank within its src
__device__ int          g_bsum[SCAN_NB];              // block-offset table (784B)
__device__ int2         g_csr[N_EDGES];               // (dst, exp_bits) packed
__device__ int          g_cnt;                        // scan ticket (self-resetting)

// packed f32x2 helpers (FFMA2 path — sm_103a)
__device__ __forceinline__ void ffma2(unsigned long long& d,
                                      unsigned long long a,
                                      unsigned long long b) {
    asm("fma.rn.f32x2 %0, %1, %2, %0;" : "+l"(d) : "l"(a), "l"(b));
}
__device__ __forceinline__ unsigned long long dup_f32(float f) {
    unsigned long long r;
    asm("mov.b64 %0, {%1, %1};" : "=l"(r) : "f"(f));
    return r;
}
__device__ __forceinline__ void unpack2(unsigned long long p, float& lo, float& hi) {
    asm("mov.b64 {%0, %1}, %2;" : "=f"(lo), "=f"(hi) : "l"(p));
}

// block-wide exclusive scan over 256 threads
__device__ __forceinline__ int block_excl_scan_256(int v) {
    __shared__ int wt[8];
    const int tid  = threadIdx.x;
    const int lane = tid & 31;
    const int wid  = tid >> 5;
    int inc = v;
#pragma unroll
    for (int o = 1; o < 32; o <<= 1) {
        int y = __shfl_up_sync(0xFFFFFFFFu, inc, o);
        if (lane >= o) inc += y;
    }
    if (lane == 31) wt[wid] = inc;
    __syncthreads();
    if (tid == 0) {
        int r = 0;
#pragma unroll
        for (int w = 0; w < 8; w++) { int t = wt[w]; wt[w] = r; r += t; }
    }
    __syncthreads();
    return inc - v + wt[wid];
}

// ---------------- K1: hybrid — gemm(+s,t) blocks | degree+rank blocks --------
#define GBM 128
#define GBK 32
__global__ void __launch_bounds__(128) gemm_deg_kernel(const float* __restrict__ x,
                                                       const float* __restrict__ W,
                                                       const float* __restrict__ attn,
                                                       const int* __restrict__ edge) {
    __shared__ float xs[GBK][GBM + 4];
    __shared__ float ws[GBK][64];

    if (blockIdx.x >= NGB) {
        // ---- degree-count + rank-capture role ----
        int b = blockIdx.x - NGB;
        for (int e = b * 128 + threadIdx.x; e < N_EDGES; e += DEGB * 128)
            g_rank[e] = atomicAdd(&g_deg[edge[e]], 1);
        return;
    }

    // ---- gemm role ----
    const int tid = threadIdx.x;
    const int tx = tid >> 3;            // 0..15 : m-tile
    const int ty = tid & 7;             // 0..7  : n-tile
    const int block_row = blockIdx.x * GBM;

    unsigned long long acc2[8][4];
#pragma unroll
    for (int i = 0; i < 8; i++)
#pragma unroll
        for (int j = 0; j < 4; j++) acc2[i][j] = 0ull;

    for (int kb = 0; kb < IN_DIM; kb += GBK) {
#pragma unroll
        for (int r = 0; r < 8; r++) {
            int idx = r * 128 + tid;
            int m   = idx >> 3;
            int k4  = (idx & 7) * 4;
            int grow = block_row + m;
            float4 v = make_float4(0.f, 0.f, 0.f, 0.f);
            if (grow < N_NODES)
                v = *reinterpret_cast<const float4*>(&x[(size_t)grow * IN_DIM + kb + k4]);
            xs[k4 + 0][m] = v.x;
            xs[k4 + 1][m] = v.y;
            xs[k4 + 2][m] = v.z;
            xs[k4 + 3][m] = v.w;
        }
#pragma unroll
        for (int r = 0; r < 4; r++) {
            int idx = r * 128 + tid;
            int k   = idx >> 4;
            int n4  = (idx & 15) * 4;
            *reinterpret_cast<float4*>(&ws[k][n4]) =
                *reinterpret_cast<const float4*>(&W[(size_t)(kb + k) * OUT_DIM + n4]);
        }
        __syncthreads();

#pragma unroll
        for (int k = 0; k < GBK; k++) {
            float a[8];
            *reinterpret_cast<float4*>(&a[0]) = *reinterpret_cast<float4*>(&xs[k][tx * 8]);
            *reinterpret_cast<float4*>(&a[4]) = *reinterpret_cast<float4*>(&xs[k][tx * 8 + 4]);
            unsigned long long b2[4];
            float4 bv0 = *reinterpret_cast<float4*>(&ws[k][ty * 8]);
            float4 bv1 = *reinterpret_cast<float4*>(&ws[k][ty * 8 + 4]);
            asm("mov.b64 %0, {%1, %2};" : "=l"(b2[0]) : "f"(bv0.x), "f"(bv0.y));
            asm("mov.b64 %0, {%1, %2};" : "=l"(b2[1]) : "f"(bv0.z), "f"(bv0.w));
            asm("mov.b64 %0, {%1, %2};" : "=l"(b2[2]) : "f"(bv1.x), "f"(bv1.y));
            asm("mov.b64 %0, {%1, %2};" : "=l"(b2[3]) : "f"(bv1.z), "f"(bv1.w));
            unsigned long long ad[8];
#pragma unroll
            for (int i = 0; i < 8; i++) ad[i] = dup_f32(a[i]);
#pragma unroll
            for (int i = 0; i < 8; i++)
#pragma unroll
                for (int j = 0; j < 4; j++) ffma2(acc2[i][j], ad[i], b2[j]);
        }
        __syncthreads();
    }

    float acc[8][8];
#pragma unroll
    for (int i = 0; i < 8; i++)
#pragma unroll
        for (int j = 0; j < 4; j++) unpack2(acc2[i][j], acc[i][2 * j], acc[i][2 * j + 1]);

#pragma unroll
    for (int i = 0; i < 8; i++) {
        int row = block_row + tx * 8 + i;
        if (row < N_NODES) {
            float4 v0 = make_float4(acc[i][0], acc[i][1], acc[i][2], acc[i][3]);
            float4 v1 = make_float4(acc[i][4], acc[i][5], acc[i][6], acc[i][7]);
            *reinterpret_cast<float4*>(&g_h[(size_t)row * OUT_DIM + ty * 8])     = v0;
            *reinterpret_cast<float4*>(&g_h[(size_t)row * OUT_DIM + ty * 8 + 4]) = v1;
        }
    }

    float as[8], ad_[8];
#pragma unroll
    for (int j = 0; j < 8; j++) {
        as[j]  = attn[ty * 8 + j];
        ad_[j] = attn[64 + ty * 8 + j];
    }
#pragma unroll
    for (int i = 0; i < 8; i++) {
        float sp = 0.f, tp = 0.f;
#pragma unroll
        for (int j = 0; j < 8; j++) {
            sp = fmaf(acc[i][j], as[j], sp);
            tp = fmaf(acc[i][j], ad_[j], tp);
        }
#pragma unroll
        for (int o = 4; o; o >>= 1) {
            sp += __shfl_xor_sync(0xFFFFFFFFu, sp, o);
            tp += __shfl_xor_sync(0xFFFFFFFFu, tp, o);
        }
        if (ty == 0) {
            int row = block_row + tx * 8 + i;
            if (row < N_NODES) { g_s[row] = sp; g_t[row] = tp; }
        }
    }
}

// ---------------- K2: scanAB — local prefixes + ns pack + bsum table ---------
__global__ void __launch_bounds__(SB) scanAB_kernel() {
    __shared__ int s_last;
    int i = blockIdx.x * SB + threadIdx.x;
    int v = 0;
    if (i < N_NODES) {
        v = g_deg[i];
        g_deg[i] = 0;                       // self-reset for next graph replay
    }
    int ex = block_excl_scan_256(v);
    if (i < N_NODES) {
        g_off[i] = ex;                      // LOCAL prefix; consumers add bsum
        g_ns[i] = make_int2(ex, __float_as_int(g_s[i]));
    }
    if (threadIdx.x == SB - 1) g_bsum[blockIdx.x] = ex + v;
    __syncthreads();
    if (threadIdx.x == 0) {
        __threadfence();
        s_last = (atomicAdd(&g_cnt, 1) == SCAN_NB - 1);
    }
    __syncthreads();
    if (s_last) {
        int t = threadIdx.x;
        int bv = (t < SCAN_NB) ? g_bsum[t] : 0;
        int bex = block_excl_scan_256(bv);
        if (t < SCAN_NB) g_bsum[t] = bex;
        // boundary: final_off(N_NODES) = g_off[N_NODES] + g_bsum[N_NODES>>8]
        //         = (N_EDGES - bex[195]) + bex[195] = N_EDGES
        if (t == SCAN_NB - 1) g_off[N_NODES] = N_EDGES - bex;
        if (t == 0) g_cnt = 0;
    }
}

// ---------------- K3: CSR fill, atomic-free, stores exp directly -------------
__global__ void __launch_bounds__(256) fill_kernel(const int* __restrict__ edge) {
    int e = blockIdx.x * 256 + threadIdx.x;
    if (e >= N_EDGES) return;
    int src  = edge[e];
    int dst  = edge[N_EDGES + e];
    int rank = g_rank[e];
    int2 ns  = g_ns[src];                      // one 8B random load: (local off, s)
    int  off = ns.x + g_bsum[src >> 8];        // bsum: 784B table, L1-resident
    float v  = __int_as_float(ns.y) + g_t[dst];
    float a  = (v >= 0.0f) ? v : ALPHA * v;
    // no global-max subtraction: exp(a) stays in fp32 range; deviation vs
    // reference bounded by ~EPS/rowsum ~ 1e-6 << 1e-3 tolerance
    g_csr[off + rank] = make_int2(dst, __float_as_int(__expf(a)));
}

// ---------------- K4: half-warp-per-node aggregate, float4 lanes, unroll 4 ---
__global__ void aggr_kernel(float* __restrict__ out) {
    int gid  = blockIdx.x * blockDim.x + threadIdx.x;
    int node = gid >> 4;                 // 16 lanes per node
    int lane = gid & 15;                 // lane covers 4 floats
    if (node >= N_NODES) return;

    int beg = g_off[node]     + g_bsum[node >> 8];
    int end = g_off[node + 1] + g_bsum[(node + 1) >> 8];

    const float4* __restrict__ h4 = reinterpret_cast<const float4*>(g_h);
    float4 acc = make_float4(0.f, 0.f, 0.f, 0.f);
    float rs = 0.f;

    int j = beg;
    for (; j + 4 <= end; j += 4) {
        int2 q0 = g_csr[j + 0], q1 = g_csr[j + 1];
        int2 q2 = g_csr[j + 2], q3 = g_csr[j + 3];
        float e0 = __int_as_float(q0.y);
        float e1 = __int_as_float(q1.y);
        float e2 = __int_as_float(q2.y);
        float e3 = __int_as_float(q3.y);
        rs += (e0 + e1) + (e2 + e3);
        float4 v0 = h4[(size_t)q0.x * 16 + lane];
        float4 v1 = h4[(size_t)q1.x * 16 + lane];
        float4 v2 = h4[(size_t)q2.x * 16 + lane];
        float4 v3 = h4[(size_t)q3.x * 16 + lane];
        acc.x = fmaf(e0, v0.x, acc.x); acc.y = fmaf(e0, v0.y, acc.y);
        acc.z = fmaf(e0, v0.z, acc.z); acc.w = fmaf(e0, v0.w, acc.w);
        acc.x = fmaf(e1, v1.x, acc.x); acc.y = fmaf(e1, v1.y, acc.y);
        acc.z = fmaf(e1, v1.z, acc.z); acc.w = fmaf(e1, v1.w, acc.w);
        acc.x = fmaf(e2, v2.x, acc.x); acc.y = fmaf(e2, v2.y, acc.y);
        acc.z = fmaf(e2, v2.z, acc.z); acc.w = fmaf(e2, v2.w, acc.w);
        acc.x = fmaf(e3, v3.x, acc.x); acc.y = fmaf(e3, v3.y, acc.y);
        acc.z = fmaf(e3, v3.z, acc.z); acc.w = fmaf(e3, v3.w, acc.w);
    }
    for (; j < end; j++) {
        int2 q = g_csr[j];
        float e = __int_as_float(q.y);
        rs += e;
        float4 v = h4[(size_t)q.x * 16 + lane];
        acc.x = fmaf(e, v.x, acc.x); acc.y = fmaf(e, v.y, acc.y);
        acc.z = fmaf(e, v.z, acc.z); acc.w = fmaf(e, v.w, acc.w);
    }
    float inv = 1.0f / (rs + GAT_EPS);
    reinterpret_cast<float4*>(out)[(size_t)node * 16 + lane] =
        make_float4(acc.x * inv, acc.y * inv, acc.z * inv, acc.w * inv);
}

// ---------------- launch ------------------------------------------------------
extern "C" void kernel_launch(void* const* d_in, const int* in_sizes, int n_in,
                              void* d_out, int out_size) {
    const float* x    = (const float*)d_in[0];
    const int*   edge = (const int*)  d_in[1];
    const float* W    = (const float*)d_in[2];
    const float* attn = (const float*)d_in[3];
    float*       out  = (float*)d_out;

    gemm_deg_kernel<<<NGB + DEGB, 128>>>(x, W, attn, edge);
    scanAB_kernel<<<SCAN_NB, SB>>>();
    fill_kernel<<<(N_EDGES + 255) / 256, 256>>>(edge);
    aggr_kernel<<<(N_NODES * 16 + 255) / 256, 256>>>(out);
}